// round 15
// baseline (speedup 1.0000x reference)
#include <cuda_runtime.h>
#include <cuda_bf16.h>

#define SORTN  2048
#define MAXIMG 8
#define ECAP   1024
#define CAP    256          // per-rank forward-degree capacity (true avg ~29)
#define BIGK   (1 << 20)    // killer sentinel for survivors

typedef unsigned long long u64;

// ---------------- persistent scratch (gmem) ----------------
__device__ u64    g_keys [MAXIMG * SORTN];
__device__ float4 g_rbox [MAXIMG * SORTN];            // bbox by score rank
__device__ float4 g_rpred[MAXIMG * SORTN];            // pred by score rank
__device__ float2 g_rmeta[MAXIMG * SORTN];            // {score, gt_bits}
__device__ float4 g_rows [(size_t)MAXIMG * SORTN * CAP]; // candidate records
__device__ int    g_deg  [MAXIMG * SORTN];
__device__ int    g_killer[MAXIMG * SORTN];
__device__ int    g_V[MAXIMG];
__device__ int    g_edgeCnt[MAXIMG];
__device__ int    g_edges[MAXIMG * ECAP];
__device__ int    g_stop[MAXIMG];
__device__ unsigned long long g_accPull[MAXIMG], g_accPush[MAXIMG];
__device__ int    g_cntPull[MAXIMG], g_cntPush[MAXIMG];
__device__ int    g_pairDone[MAXIMG];
__device__ int    g_done;

// pinned arithmetic — identical intrinsic sequence everywhere (bit-exact
// agreement across kernels preserves the sequential greedy trajectory)
__device__ __forceinline__ float dist4(float4 e, float4 w)
{
    float d0 = e.x - w.x, d1 = e.y - w.y, d2 = e.z - w.z, d3 = e.w - w.w;
    return 0.25f * __fmaf_rn(d3, d3, __fmaf_rn(d2, d2,
                    __fmaf_rn(d1, d1, __fmul_rn(d0, d0))));
}
__device__ __forceinline__ bool boxov(float4 e, float4 w)
{
    return (fminf(e.z, w.z) > fmaxf(e.x, w.x))
        && (fminf(e.w, w.w) > fmaxf(e.y, w.y));
}

// =====================================================================
// K0: keys — validity + descending-sortable key; reset all counters
// =====================================================================
__global__ __launch_bounds__(256)
void key_kernel(const int* __restrict__ gt, const float* __restrict__ prop,
                int N, int imgs)
{
    int idx = blockIdx.x * 256 + threadIdx.x;
    int img = idx >> 11, j = idx & (SORTN - 1);
    if (img >= imgs) return;
    u64 key = 0ull;
    if (j < N) {
        const float* pr = prop + ((size_t)img * N + j) * 5;
        float y1 = pr[1], y2 = pr[3], S = pr[4];
        int g = gt[img * N + j];
        if (g >= 0 && (y2 - y1) > 0.f)
            key = ((u64)__float_as_uint(S) << 32)
                | (u64)(unsigned)(~j);          // ties: smaller idx first
    }
    g_keys[img * SORTN + j] = key;
    if (j == 0) { g_edgeCnt[img] = 0; g_pairDone[img] = 0; }  // replay-safe
    if (idx == 0) g_done = 0;
}

// =====================================================================
// K1: rank by counting (warp per element, 128-bit key loads) + scatter
// =====================================================================
__global__ __launch_bounds__(256)
void rank_kernel(const float* __restrict__ pred, const int* __restrict__ gt,
                 const float* __restrict__ prop, int N, int imgs)
{
    int wid  = blockIdx.x * 8 + (threadIdx.x >> 5);
    int lane = threadIdx.x & 31;
    int img  = wid >> 11, e = wid & (SORTN - 1);
    if (img >= imgs) return;
    const u64* keys = g_keys + img * SORTN;
    u64 myk = keys[e];

    const ulonglong2* k2 = reinterpret_cast<const ulonglong2*>(keys);
    int rank = 0, vcnt = 0;
    #pragma unroll 4
    for (int j = lane; j < SORTN / 2; j += 32) {
        ulonglong2 kk = k2[j];
        rank += (int)(kk.x > myk) + (int)(kk.y > myk);   // keys unique
        vcnt += (int)(kk.x != 0ull) + (int)(kk.y != 0ull);
    }
    #pragma unroll
    for (int off = 16; off; off >>= 1) {
        rank += __shfl_xor_sync(0xffffffffu, rank, off);
        vcnt += __shfl_xor_sync(0xffffffffu, vcnt, off);
    }
    if (lane == 0) {
        if (e == 0) g_V[img] = vcnt;
        if (myk != 0ull) {
            int j = (int)~((unsigned)myk);      // recover original index
            const float* pr = prop + ((size_t)img * N + j) * 5;
            int base = img * SORTN;
            g_rbox [base + rank] = make_float4(pr[0], pr[1], pr[2], pr[3]);
            g_rpred[base + rank] =
                reinterpret_cast<const float4*>(pred + (size_t)img * N * 4)[j];
            g_rmeta[base + rank] = make_float2(pr[4],
                                               __int_as_float(gt[img * N + j]));
        }
    }
}

// =====================================================================
// Embedded sweep (runs on the LAST pair CTA per image). All __shared__
// storage is FUNCTION-SCOPE (allocated per-CTA for pair_kernel).
// Counting-sort edges by (hi,lo), pointer-walk first-killer fixpoint
// (1 barrier/round), stop-rank via prefix sums, publish killer ranks.
// Exact = serial replay: when edge (lo,h) is reached in ascending order,
// lo's fate is final, so killer(h) = first ALIVE source with all smaller
// sources DEAD.
// =====================================================================
__device__ void sweep_image(int img)
{
    __shared__ int   s_ebuf[ECAP];          // raw (hi<<11)|lo
    __shared__ int   s_srt [ECAP];          // sorted ascending
    __shared__ unsigned char s_stat[SORTN]; // 0 undecided, 1 alive, 2 dead
    __shared__ short s_kil [SORTN];
    __shared__ short s_cur [SORTN], s_hend[SORTN];
    __shared__ int   s_delta[SORTN];
    __shared__ int   s_wtot[8], s_wpre[8];
    __shared__ int   s_und[2];
    __shared__ int   s_stop;

    const int t = threadIdx.x, lane = t & 31, w = t >> 5;
    const int V = g_V[img];
    int E = g_edgeCnt[img]; if (E > ECAP) E = ECAP;

    for (int i = t; i < E; i += 256) {
        int key = g_edges[img * ECAP + i];                 // (lo<<11)|hi
        s_ebuf[i] = ((key & (SORTN - 1)) << 11) | (key >> 11);
    }
    for (int i = t; i < SORTN; i += 256) { s_stat[i] = 1; s_kil[i] = 0; s_delta[i] = 0; }
    if (t == 0) {
        s_stop = V; s_und[0] = 0; s_und[1] = 0;
        g_accPull[img] = 0ull; g_accPush[img] = 0ull;      // per-launch reset
        g_cntPull[img] = 0;    g_cntPush[img] = 0;
    }
    __syncthreads();

    // counting-rank: unique (hi,lo) keys => exact ascending permutation,
    // canonical regardless of nondeterministic atomic append order
    for (int i = t; i < E; i += 256) {
        int ki = s_ebuf[i], rk = 0;
        for (int j = 0; j < E; j++) rk += (int)(s_ebuf[j] < ki);
        s_srt[rk] = ki;
    }
    __syncthreads();
    for (int i = t; i < E; i += 256) s_stat[s_srt[i] >> 11] = 0;  // has in-edge
    __syncthreads();
    for (int i = t; i < E; i += 256) {                     // segment bounds per h
        int h = s_srt[i] >> 11;
        if (i == 0     || (s_srt[i-1] >> 11) != h) s_cur [h] = (short)i;
        if (i == E - 1 || (s_srt[i+1] >> 11) != h) s_hend[h] = (short)(i + 1);
    }
    __syncthreads();

    // pointer-walk fixpoint: stat transitions are monotone (0->1, 0->2),
    // so intra-round races only delay a decision (stays exact). The
    // globally smallest undecided victim has all sources decided (they are
    // smaller ranks) => >=1 decision per round => terminates in <= E rounds.
    for (int round = 0; round < ECAP + 4; round++) {
        int cb = round & 1;
        for (int i = t; i < E; i += 256) {
            int h = s_srt[i] >> 11;
            if ((i == 0 || (s_srt[i-1] >> 11) != h) && s_stat[h] == 0) {
                int p = s_cur[h], pe = s_hend[h];
                while (p < pe && s_stat[s_srt[p] & (SORTN - 1)] == 2) p++;
                if (p == pe) s_stat[h] = 1;                // all killers dead
                else {
                    int lo = s_srt[p] & (SORTN - 1);
                    if (s_stat[lo] == 1) { s_stat[h] = 2; s_kil[h] = (short)lo; }
                    else { s_cur[h] = (short)p; s_und[cb] = 1; }
                }
            }
        }
        if (t == 0) s_und[cb ^ 1] = 0;
        __syncthreads();                                   // ONE barrier/round
        if (!s_und[cb]) break;
    }

    // delta: f(w)+=1 for w in (killer, victim)
    for (int v = t; v < SORTN; v += 256)
        if (s_stat[v] == 2) {
            atomicAdd(&s_delta[(int)s_kil[v] + 1],  1);
            atomicAdd(&s_delta[v],                 -1);
        }
    __syncthreads();

    // parallel prefix: per-thread 8-chunk, warp shfl scan, 8-way combine
    int loc[8], s = 0;
    #pragma unroll
    for (int i = 0; i < 8; i++) { s += s_delta[t * 8 + i]; loc[i] = s; }
    int incl = s;
    #pragma unroll
    for (int o = 1; o < 32; o <<= 1) {
        int n = __shfl_up_sync(0xffffffffu, incl, o);
        if (lane >= o) incl += n;
    }
    if (lane == 31) s_wtot[w] = incl;
    __syncthreads();
    if (t == 0) { int a = 0; for (int i = 0; i < 8; i++) { s_wpre[i] = a; a += s_wtot[i]; } }
    __syncthreads();
    int off = s_wpre[w] + (incl - s);

    int myStop = V;
    #pragma unroll
    for (int i = 0; i < 8; i++) {
        int w2 = t * 8 + i;
        if (w2 < V && s_stat[w2] != 2) {
            int cnt = V - w2 - (off + loc[i]);             // alive before step w2
            if (cnt <= 1 && w2 < myStop) myStop = w2;
        }
    }
    atomicMin(&s_stop, myStop);
    __syncthreads();

    for (int i = t; i < SORTN; i += 256)
        g_killer[img * SORTN + i] = (s_stat[i] == 2) ? (int)s_kil[i] : BIGK;
    if (t == 0) g_stop[img] = s_stop;
}

// =====================================================================
// K2: pairs — warp per rank lo, scan e>lo once: deterministic candidate
//     rows + d<0.1 edges. LAST CTA per image runs the embedded sweep
//     (election pattern proven by the fused combine in R11/R12).
// =====================================================================
__global__ __launch_bounds__(256)
void pair_kernel(int imgs)
{
    __shared__ int s_lastFlag;

    int wid  = blockIdx.x * 8 + (threadIdx.x >> 5);
    int lane = threadIdx.x & 31;
    int img  = wid >> 11, lo = wid & (SORTN - 1);
    if (img >= imgs) return;
    int V = g_V[img];
    const int base = img * SORTN;

    if (lo < V) {
        float4 wb = g_rbox[base + lo], wp = g_rpred[base + lo];
        float2 wm = g_rmeta[base + lo];
        int wgt = __float_as_int(wm.y);
        float4* row = g_rows + (size_t)(base + lo) * CAP;

        int cnt = 0;
        for (int eb0 = lo + 1; eb0 < V; eb0 += 32) {
            int e = eb0 + lane;
            bool ov = false;
            if (e < V) ov = boxov(g_rbox[base + e], wb);   // 16B-only fast path
            unsigned bal = __ballot_sync(0xffffffffu, ov);
            if (ov) {                                      // ~3% of lanes
                float4 ep = g_rpred[base + e];
                float2 em = g_rmeta[base + e];
                float d = dist4(ep, wp);
                bool same = (__float_as_int(em.y) == wgt);
                int pos = cnt + __popc(bal & ((1u << lane) - 1u)); // deterministic
                if (pos < CAP)
                    row[pos] = make_float4(d, em.x,
                                __int_as_float(e | (same ? 4096 : 0)), 0.f);
                if (d < 0.1f) {                            // suppression edge
                    int p = atomicAdd(&g_edgeCnt[img], 1); // set is deterministic
                    if (p < ECAP) g_edges[img * ECAP + p] = (lo << 11) | e;
                }
            }
            cnt += __popc(bal);
        }
        if (lane == 0) g_deg[base + lo] = (cnt < CAP) ? cnt : CAP;
    } else if (lane == 0) {
        g_deg[base + lo] = 0;
    }

    // last-CTA-per-image election: 256 pair CTAs per image
    __syncthreads();
    if (threadIdx.x == 0) {
        __threadfence();                                   // publish edges/rows
        s_lastFlag = (atomicAdd(&g_pairDone[img], 1) == 255);
        if (s_lastFlag) __threadfence();                   // acquire-side hardening
    }
    __syncthreads();
    if (s_lastFlag) sweep_image(img);
}

// =====================================================================
// K3: sums + fused combine — warp per winner over its candidate row;
//     last CTA (threadfence + atomic counter) writes the output.
//     Element e is in rem at step r iff killer(e) >= r (== r: suppressed
//     THIS step, still in rem — matches reference's post-mask order).
// =====================================================================
__global__ __launch_bounds__(256, 4)
void sums_kernel(float* __restrict__ out, int imgs, int nCTA)
{
    int wid  = blockIdx.x * 8 + (threadIdx.x >> 5);
    int lane = threadIdx.x & 31;
    int img  = wid >> 11, r = wid & (SORTN - 1);
    const int base = img * SORTN;

    bool win = (img < imgs) && (r < g_stop[img]) && (g_killer[base + r] >= BIGK);
    if (win) {
        int deg = g_deg[base + r];
        const float4* row = g_rows + (size_t)(base + r) * CAP;

        float pull = 0.f, push = 0.f;
        int pn = 0, qn = 0;
        for (int i = lane; i < deg; i += 32) {
            float4 rec = row[i];
            int fl = __float_as_int(rec.z);
            int e  = fl & (SORTN - 1);
            bool same    = (fl & 4096) != 0;
            bool aliveAt = (g_killer[base + e] >= r);      // L1-hot 8KB gather
            float d = rec.x;
            bool check = d < 0.1f;
            if (aliveAt && same && !check) { pull = fmaf(d, rec.y, pull); pn++; }
            if (aliveAt && !same && check) {
                float t1 = fmaf(d, -0.16666667f, 0.5f);    // exp(-d), d<0.1, Taylor-3
                float ex = fmaf(d * d, t1, 1.0f - d);
                push = fmaf(ex, rec.y, push); qn++;
            }
        }
        #pragma unroll
        for (int off = 16; off; off >>= 1) {
            pull += __shfl_xor_sync(0xffffffffu, pull, off);
            push += __shfl_xor_sync(0xffffffffu, push, off);
            pn   += __shfl_xor_sync(0xffffffffu, pn,   off);
            qn   += __shfl_xor_sync(0xffffffffu, qn,   off);
        }
        if (lane == 0) {
            if (pn > 0) {                                  // fixed-point: associative
                float v = pull / (float)pn;                // => deterministic atomics
                atomicAdd(&g_accPull[img],
                          (unsigned long long)__float2ll_rn(v * 1048576.0f));
                atomicAdd(&g_cntPull[img], 1);
            }
            if (qn > 0) {
                float v = push / (float)qn;
                atomicAdd(&g_accPush[img],
                          (unsigned long long)__float2ll_rn(v * 1048576.0f));
                atomicAdd(&g_cntPush[img], 1);
            }
        }
    }

    __syncthreads();                                       // all CTA atomics issued
    if (threadIdx.x == 0) {
        __threadfence();                                   // publish before arrival
        if (atomicAdd(&g_done, 1) == nCTA - 1) {           // last CTA combines
            float ps = 0.f, pl = 0.f;
            for (int i = 0; i < imgs; i++) {
                float pushT = (float)(long long)g_accPush[i] * (1.0f/1048576.0f);
                float pullT = (float)(long long)g_accPull[i] * (1.0f/1048576.0f);
                ps += pushT / ((float)g_cntPush[i] + 1e-6f);
                pl += pullT / ((float)g_cntPull[i] + 1e-6f);
            }
            out[0] = ps / (float)imgs;                     // push_loss (weight 1)
            out[1] = pl / (float)imgs;                     // pull_loss (weight 1)
        }
    }
}

extern "C" void kernel_launch(void* const* d_in, const int* in_sizes, int n_in,
                              void* d_out, int out_size)
{
    const float* pred = (const float*)d_in[0];   // (IMGS, N, 4)
    const int*   gt   = (const int*)  d_in[1];   // (IMGS, N)
    const float* prop = (const float*)d_in[2];   // (IMGS, N, 5)

    int imgs = 4, N = 2000;
    if (n_in >= 4 && in_sizes[3] > 0 && in_sizes[3] % 80 == 0)
        imgs = in_sizes[3] / 80;
    if (imgs > 0 && in_sizes[1] % imgs == 0)
        N = in_sizes[1] / imgs;
    if (imgs > MAXIMG) imgs = MAXIMG;
    if (N > SORTN) N = SORTN;

    key_kernel  <<<imgs * 8,   256>>>(gt, prop, N, imgs);
    rank_kernel <<<imgs * 256, 256>>>(pred, gt, prop, N, imgs);
    pair_kernel <<<imgs * 256, 256>>>(imgs);
    sums_kernel <<<imgs * 256, 256>>>((float*)d_out, imgs, imgs * 256);
}